// round 14
// baseline (speedup 1.0000x reference)
#include <cuda_runtime.h>
#include <cuda_fp16.h>
#include <math.h>
#include <stdint.h>

// Problem constants
#define BATCH 2
#define SEQ   2048
#define DMODEL 1024
#define NHEAD 16
#define HDIM  64
#define FFDIM 4096
#define MROWS (BATCH*SEQ)   // 4096
#define LN_EPS 1e-5f

// ---------------- scratch buffers ------------------------------------------
__device__ float g_xn [MROWS*DMODEL];
__device__ float g_r1 [MROWS*DMODEL];
__device__ float g_y  [MROWS*DMODEL];

__device__ __half g_xnh[MROWS*DMODEL];
__device__ __half g_yh [MROWS*DMODEL];
__device__ __half g_qh [MROWS*DMODEL];
__device__ __half g_kh [MROWS*DMODEL];
__device__ __half g_vh [MROWS*DMODEL];
__device__ __half g_ath[MROWS*DMODEL];
__device__ __half g_hh [MROWS*FFDIM];

__device__ __half g_wqkvh[3*DMODEL*DMODEL];   // concat q,k,v weights
__device__ float  g_bqkv [3*DMODEL];          // concat q,k,v biases
__device__ __half g_woh[DMODEL*DMODEL];
__device__ __half g_w1h[FFDIM*DMODEL];
__device__ __half g_w2h[DMODEL*FFDIM];

// ---------------- helpers ---------------------------------------------------
__device__ __forceinline__ uint32_t smem_to_u32(const void* p) {
    uint32_t a;
    asm("{ .reg .u64 t; cvta.to.shared.u64 t, %1; cvt.u32.u64 %0, t; }"
        : "=r"(a) : "l"(p));
    return a;
}
__device__ __forceinline__ void cp16(uint32_t d, const void* s) {
    asm volatile("cp.async.cg.shared.global [%0], [%1], 16;" :: "r"(d), "l"(s) : "memory");
}
#define CP_COMMIT() asm volatile("cp.async.commit_group;" ::: "memory")
#define CP_WAIT0()  asm volatile("cp.async.wait_group 0;" ::: "memory")
#define CP_WAIT1()  asm volatile("cp.async.wait_group 1;" ::: "memory")

__device__ __forceinline__ void ldsm4(uint32_t* r, uint32_t addr) {
    asm volatile("ldmatrix.sync.aligned.m8n8.x4.shared.b16 {%0,%1,%2,%3}, [%4];"
        : "=r"(r[0]), "=r"(r[1]), "=r"(r[2]), "=r"(r[3]) : "r"(addr));
}
__device__ __forceinline__ void ldsm4t(uint32_t* r, uint32_t addr) {
    asm volatile("ldmatrix.sync.aligned.m8n8.x4.trans.shared.b16 {%0,%1,%2,%3}, [%4];"
        : "=r"(r[0]), "=r"(r[1]), "=r"(r[2]), "=r"(r[3]) : "r"(addr));
}
__device__ __forceinline__ void mma16816(float* c, const uint32_t* a,
                                         uint32_t b0, uint32_t b1) {
    asm volatile("mma.sync.aligned.m16n8k16.row.col.f32.f16.f16.f32 "
        "{%0,%1,%2,%3}, {%4,%5,%6,%7}, {%8,%9}, {%0,%1,%2,%3};"
        : "+f"(c[0]), "+f"(c[1]), "+f"(c[2]), "+f"(c[3])
        : "r"(a[0]), "r"(a[1]), "r"(a[2]), "r"(a[3]), "r"(b0), "r"(b1));
}

__device__ __forceinline__ uint32_t pack_hf2(float a, float b) {
    __half2 t;
    t.x = __float2half_rn(a);
    t.y = __float2half_rn(b);
    uint32_t u;
    *reinterpret_cast<__half2*>(&u) = t;
    return u;
}
__device__ __forceinline__ float gelu_exact(float v) {
    return 0.5f * v * (1.0f + erff(v * 0.70710678118654752440f));
}

// ---------------- fused weight converts --------------------------------------
#define DD4 (DMODEL*DMODEL/4)
__global__ __launch_bounds__(256)
void conv_qkv_kernel(const float* __restrict__ wq, const float* __restrict__ wk,
                     const float* __restrict__ wv, const float* __restrict__ bq,
                     const float* __restrict__ bk, const float* __restrict__ bv,
                     __half* __restrict__ dst, float* __restrict__ bdst)
{
    int i = blockIdx.x * blockDim.x + threadIdx.x;
    if (i < 3 * DMODEL / 4) {
        int seg = i / (DMODEL/4), li = i % (DMODEL/4);
        const float* src = (seg == 0) ? bq : (seg == 1) ? bk : bv;
        reinterpret_cast<float4*>(bdst)[i] = reinterpret_cast<const float4*>(src)[li];
    }
    if (i >= 3 * DD4) return;
    int seg = i / DD4, li = i % DD4;
    const float* src = (seg == 0) ? wq : (seg == 1) ? wk : wv;
    float4 v = reinterpret_cast<const float4*>(src)[li];
    uint2 hu;
    hu.x = pack_hf2(v.x, v.y);
    hu.y = pack_hf2(v.z, v.w);
    reinterpret_cast<uint2*>(dst)[i] = hu;
}

#define FD4 (FFDIM*DMODEL/4)
__global__ __launch_bounds__(256)
void conv_rest_kernel(const float* __restrict__ wo, const float* __restrict__ w1,
                      const float* __restrict__ w2, __half* __restrict__ oh,
                      __half* __restrict__ h1, __half* __restrict__ h2)
{
    int i = blockIdx.x * blockDim.x + threadIdx.x;
    if (i >= DD4 + 2 * FD4) return;
    const float* src; __half* dst; int li;
    if (i < DD4)            { src = wo; dst = oh; li = i; }
    else if (i < DD4 + FD4) { src = w1; dst = h1; li = i - DD4; }
    else                    { src = w2; dst = h2; li = i - DD4 - FD4; }
    float4 v = reinterpret_cast<const float4*>(src)[li];
    uint2 hu;
    hu.x = pack_hf2(v.x, v.y);
    hu.y = pack_hf2(v.z, v.w);
    reinterpret_cast<uint2*>(dst)[li] = hu;
}

// ---------------- LayerNorm + fp16 out ---------------------------------------
__global__ __launch_bounds__(256)
void ln_conv_kernel(const float* __restrict__ x, const float* __restrict__ g,
                    const float* __restrict__ b, float* __restrict__ y,
                    __half* __restrict__ yh)
{
    int row = blockIdx.x;
    int tid = threadIdx.x;
    const float4* xr = reinterpret_cast<const float4*>(x + (size_t)row * DMODEL);
    float4 v = xr[tid];

    float s = v.x + v.y + v.z + v.w;
    float q = v.x*v.x + v.y*v.y + v.z*v.z + v.w*v.w;
    #pragma unroll
    for (int o = 16; o > 0; o >>= 1) {
        s += __shfl_down_sync(0xffffffffu, s, o);
        q += __shfl_down_sync(0xffffffffu, q, o);
    }
    __shared__ float ss[8], sq[8];
    int wid = tid >> 5, lane = tid & 31;
    if (lane == 0) { ss[wid] = s; sq[wid] = q; }
    __syncthreads();
    float tot = 0.f, totq = 0.f;
    #pragma unroll
    for (int i = 0; i < 8; ++i) { tot += ss[i]; totq += sq[i]; }

    float mu  = tot * (1.0f / DMODEL);
    float var = totq * (1.0f / DMODEL) - mu * mu;
    float rs  = rsqrtf(var + LN_EPS);

    float4 gg = reinterpret_cast<const float4*>(g)[tid];
    float4 bb = reinterpret_cast<const float4*>(b)[tid];
    float4 o;
    o.x = (v.x - mu) * rs * gg.x + bb.x;
    o.y = (v.y - mu) * rs * gg.y + bb.y;
    o.z = (v.z - mu) * rs * gg.z + bb.z;
    o.w = (v.w - mu) * rs * gg.w + bb.w;
    reinterpret_cast<float4*>(y + (size_t)row * DMODEL)[tid] = o;

    uint2 hu;
    hu.x = pack_hf2(o.x, o.y);
    hu.y = pack_hf2(o.z, o.w);
    reinterpret_cast<uint2*>(yh + (size_t)row * DMODEL)[tid] = hu;
}

// ---------------- warp-MMA GEMM: 128x128 CTA, KC=64, 2-stage -----------------
#define EPI_RES    1
#define EPI_GELUS  2
#define EPI_QKV3   5

#define GROWB2 144                      // bytes per 64-elem row (128 + 16 pad)
#define OFF_W  (128 * GROWB2)           // W rows follow 128 A rows
#define STAGEB (256 * GROWB2)           // 36864
#define GEMM_SMEM (2*STAGEB)            // 73728 -> 2 CTAs = 147456

template<int EPI>
__global__ __launch_bounds__(256, 2)
void gemm_mma(const __half* __restrict__ A, const __half* __restrict__ W,
              const float* __restrict__ bias, const float* __restrict__ res,
              float* __restrict__ Cf, __half* __restrict__ Chi,
              __half* __restrict__ C2, __half* __restrict__ C3,
              int M, int N, int K)
{
    extern __shared__ char smc[];
    uint32_t sb = smem_to_u32(smc);
    int tid  = threadIdx.x;
    int lane = tid & 31;
    int warp = tid >> 5;
    int n0 = blockIdx.x * 128;
    int m0 = blockIdx.y * 128;
    int wm = (warp >> 2) * 64;
    int wn = (warp & 3) * 32;

    // loader: row r = tid>>1 (0..127), k-half hf = tid&1 (32 elems = 64B = 4 cp16)
    int r  = tid >> 1;
    int hf = tid & 1;
    const __half* gA = A + (size_t)(m0 + r) * K + hf * 32;
    const __half* gW = W + (size_t)(n0 + r) * K + hf * 32;
    uint32_t saA = sb + r * GROWB2 + hf * 64;
    uint32_t saW = sb + OFF_W + r * GROWB2 + hf * 64;

    float acc[4][4][4];
    #pragma unroll
    for (int mi = 0; mi < 4; ++mi)
        #pragma unroll
        for (int nj = 0; nj < 4; ++nj)
            #pragma unroll
            for (int e = 0; e < 4; ++e) acc[mi][nj][e] = 0.f;

    uint32_t lmo = (uint32_t)((lane & 15) * GROWB2 + (lane >> 4) * 16);
    int nch = K / 64;

    // prologue: chunk 0 into stage 0
    {
        #pragma unroll
        for (int cchunk = 0; cchunk < 4; ++cchunk) {
            cp16(saA + cchunk * 16, gA + cchunk * 8);
            cp16(saW + cchunk * 16, gW + cchunk * 8);
        }
        CP_COMMIT();
        CP_WAIT0();
        __syncthreads();
    }

    for (int c = 0; c < nch; ++c) {
        int s = c & 1;
        // issue chunk c+1 loads into s^1 (overlap with compute below)
        if (c + 1 < nch) {
            size_t ko = (size_t)(c + 1) * 64;
            uint32_t so = (uint32_t)((s ^ 1) * STAGEB);
            #pragma unroll
            for (int cchunk = 0; cchunk < 4; ++cchunk) {
                cp16(saA + so + cchunk * 16, gA + ko + cchunk * 8);
                cp16(saW + so + cchunk * 16, gW + ko + cchunk * 8);
            }
            CP_COMMIT();
        }

        uint32_t stgb = sb + s * STAGEB;
        #pragma unroll
        for (int ks = 0; ks < 4; ++ks) {
            uint32_t kb = ks * 32;   // bytes (16 halves)
            uint32_t aF[4][4], bW[2][4];
            #pragma unroll
            for (int mi = 0; mi < 4; ++mi) {
                uint32_t ra = (wm + mi * 16) * GROWB2 + lmo + kb;
                ldsm4(aF[mi], stgb + ra);
            }
            #pragma unroll
            for (int p = 0; p < 2; ++p) {
                uint32_t rb = OFF_W + (wn + p * 16) * GROWB2 + lmo + kb;
                ldsm4(bW[p], stgb + rb);
            }
            #pragma unroll
            for (int mi = 0; mi < 4; ++mi) {
                #pragma unroll
                for (int nj = 0; nj < 4; ++nj) {
                    uint32_t b0 = bW[nj >> 1][nj & 1];
                    uint32_t b1 = bW[nj >> 1][(nj & 1) + 2];
                    mma16816(acc[mi][nj], aF[mi], b0, b1);
                }
            }
        }

        if (c + 1 < nch) {
            CP_WAIT0();
            __syncthreads();
        }
    }

    int gid  = lane >> 2;
    int tid4 = lane & 3;
    float b2v[4][2];
    #pragma unroll
    for (int nj = 0; nj < 4; ++nj) {
        int col = n0 + wn + nj * 8 + tid4 * 2;
        b2v[nj][0] = bias[col];
        b2v[nj][1] = bias[col + 1];
    }
    __half* qdst = Chi;
    if (EPI == EPI_QKV3) {
        qdst = (n0 < DMODEL) ? Chi : ((n0 < 2*DMODEL) ? C2 : C3);
    }
    #pragma unroll
    for (int mi = 0; mi < 4; ++mi) {
        #pragma unroll
        for (int half = 0; half < 2; ++half) {
            int row = m0 + wm + mi * 16 + gid + half * 8;
            #pragma unroll
            for (int nj = 0; nj < 4; ++nj) {
                int col = n0 + wn + nj * 8 + tid4 * 2;
                float v0 = acc[mi][nj][half * 2 + 0] + b2v[nj][0];
                float v1 = acc[mi][nj][half * 2 + 1] + b2v[nj][1];
                if (EPI == EPI_RES) {
                    float2 rv = *reinterpret_cast<const float2*>(&res[(size_t)row * N + col]);
                    v0 += rv.x; v1 += rv.y;
                    float2 o; o.x = v0; o.y = v1;
                    *reinterpret_cast<float2*>(&Cf[(size_t)row * N + col]) = o;
                } else if (EPI == EPI_QKV3) {
                    int lcol = col & (DMODEL - 1);
                    *reinterpret_cast<uint32_t*>(&qdst[(size_t)row * DMODEL + lcol]) = pack_hf2(v0, v1);
                } else {
                    if (EPI == EPI_GELUS) { v0 = gelu_exact(v0); v1 = gelu_exact(v1); }
                    *reinterpret_cast<uint32_t*>(&Chi[(size_t)row * N + col]) = pack_hf2(v0, v1);
                }
            }
        }
    }
}

// ---------------- MMA flash attention (3-stage KV pipeline, as R11) ----------
#define QST 72                         // smem row stride in fp16 elems (144B)
#define AQ  0
#define AKV0 (128*QST)                 // stage base
#define KVSTG (2*64*QST)               // elems per stage (K, V)
#define AOF_K 0
#define AOF_V (64*QST)
#define ATTN_SMEM ((128*QST + 3*KVSTG) * 2)   // 73728 bytes

__global__ __launch_bounds__(256, 2)
void attn_mma(const __half* __restrict__ Qh, const __half* __restrict__ Kh,
              const __half* __restrict__ Vh, __half* __restrict__ Ohi)
{
    extern __shared__ __half sma[];
    uint32_t sb = smem_to_u32(sma);

    int tid  = threadIdx.x;
    int lane = tid & 31;
    int warp = tid >> 5;
    int bh = blockIdx.y;
    int b = bh >> 4, h = bh & 15;
    int qbase  = b * SEQ + blockIdx.x * 128;
    int kvbase = b * SEQ;
    int hcol   = h * HDIM;
    int wm = warp * 16;

    int krr = tid >> 2;
    int kc4 = (tid & 3) * 16;
    uint32_t kdst = sb + (krr * QST + kc4) * 2;
    size_t kgo = (size_t)hcol + kc4;

    {
        int rr = tid >> 1, cc2 = (tid & 1) * 4;
        const __half* gq = Qh + (size_t)(qbase + rr) * DMODEL + hcol + cc2 * 8;
        uint32_t dq = sb + (rr * QST + cc2 * 8) * 2;
        #pragma unroll
        for (int c = 0; c < 4; ++c)
            cp16(dq + AQ * 2 + c * 16, gq + c * 8);

        size_t grow = (size_t)(kvbase + krr) * DMODEL + kgo;
        uint32_t st = kdst + AKV0 * 2;
        cp16(st + AOF_K*2, Kh + grow);  cp16(st + AOF_K*2 + 16, Kh + grow + 8);
        cp16(st + AOF_V*2, Vh + grow);  cp16(st + AOF_V*2 + 16, Vh + grow + 8);
        CP_COMMIT();

        grow = (size_t)(kvbase + 64 + krr) * DMODEL + kgo;
        st = kdst + (AKV0 + KVSTG) * 2;
        cp16(st + AOF_K*2, Kh + grow);  cp16(st + AOF_K*2 + 16, Kh + grow + 8);
        cp16(st + AOF_V*2, Vh + grow);  cp16(st + AOF_V*2 + 16, Vh + grow + 8);
        CP_COMMIT();
    }

    float oacc[8][4];
    #pragma unroll
    for (int j = 0; j < 8; ++j)
        #pragma unroll
        for (int e = 0; e < 4; ++e) oacc[j][e] = 0.f;
    float mrow[2] = {-1e30f, -1e30f};
    float lrow[2] = {0.f, 0.f};

    uint32_t lmo = (uint32_t)((lane & 15) * QST * 2 + (lane >> 4) * 16);
    const float scale = 0.125f;

    const int NT = SEQ / 64;
    int cs = 0;
    for (int t = 0; t < NT; ++t) {
        CP_WAIT1();
        __syncthreads();

        if (t + 2 < NT) {
            int ps = cs + 2; if (ps >= 3) ps -= 3;
            size_t grow = (size_t)(kvbase + (t + 2) * 64 + krr) * DMODEL + kgo;
            uint32_t st = kdst + (AKV0 + ps * KVSTG) * 2;
            cp16(st + AOF_K*2, Kh + grow);  cp16(st + AOF_K*2 + 16, Kh + grow + 8);
            cp16(st + AOF_V*2, Vh + grow);  cp16(st + AOF_V*2 + 16, Vh + grow + 8);
        }
        CP_COMMIT();

        uint32_t kvb = sb + (AKV0 + cs * KVSTG) * 2;

        float sacc[8][4];
        #pragma unroll
        for (int j = 0; j < 8; ++j)
            #pragma unroll
            for (int e = 0; e < 4; ++e) sacc[j][e] = 0.f;

        #pragma unroll
        for (int kk = 0; kk < 4; ++kk) {
            uint32_t aQ[4], bK[4];
            uint32_t qa = sb + wm * QST * 2 + lmo + kk * 32;
            ldsm4(aQ, qa + AQ * 2);
            #pragma unroll
            for (int p = 0; p < 4; ++p) {
                uint32_t ka = kvb + p * 16 * QST * 2 + lmo + kk * 32;
                ldsm4(bK, ka + AOF_K * 2);
                #pragma unroll
                for (int tt = 0; tt < 2; ++tt) {
                    int j = p * 2 + tt;
                    mma16816(sacc[j], aQ, bK[tt], bK[tt + 2]);
                }
            }
        }

        float alpha[2];
        #pragma unroll
        for (int hf = 0; hf < 2; ++hf) {
            float mv = mrow[hf];
            #pragma unroll
            for (int j = 0; j < 8; ++j) {
                sacc[j][2*hf]   *= scale;
                sacc[j][2*hf+1] *= scale;
                mv = fmaxf(mv, fmaxf(sacc[j][2*hf], sacc[j][2*hf+1]));
            }
            mv = fmaxf(mv, __shfl_xor_sync(0xffffffffu, mv, 1));
            mv = fmaxf(mv, __shfl_xor_sync(0xffffffffu, mv, 2));
            alpha[hf] = __expf(mrow[hf] - mv);
            float ls = 0.f;
            #pragma unroll
            for (int j = 0; j < 8; ++j) {
                sacc[j][2*hf]   = __expf(sacc[j][2*hf]   - mv);
                sacc[j][2*hf+1] = __expf(sacc[j][2*hf+1] - mv);
                ls += sacc[j][2*hf] + sacc[j][2*hf+1];
            }
            ls += __shfl_xor_sync(0xffffffffu, ls, 1);
            ls += __shfl_xor_sync(0xffffffffu, ls, 2);
            lrow[hf] = lrow[hf] * alpha[hf] + ls;
            mrow[hf] = mv;
            #pragma unroll
            for (int j = 0; j < 8; ++j) {
                oacc[j][2*hf]   *= alpha[hf];
                oacc[j][2*hf+1] *= alpha[hf];
            }
        }

        uint32_t pF[4][4];
        #pragma unroll
        for (int kk = 0; kk < 4; ++kk) {
            int j0 = 2 * kk, j1 = 2 * kk + 1;
            pF[kk][0] = pack_hf2(sacc[j0][0], sacc[j0][1]);
            pF[kk][1] = pack_hf2(sacc[j0][2], sacc[j0][3]);
            pF[kk][2] = pack_hf2(sacc[j1][0], sacc[j1][1]);
            pF[kk][3] = pack_hf2(sacc[j1][2], sacc[j1][3]);
        }

        #pragma unroll
        for (int kk = 0; kk < 4; ++kk) {
            #pragma unroll
            for (int p = 0; p < 4; ++p) {
                uint32_t va = kvb + kk * 16 * QST * 2 + lmo + p * 32;
                uint32_t vV[4];
                ldsm4t(vV, va + AOF_V * 2);
                #pragma unroll
                for (int tt = 0; tt < 2; ++tt) {
                    int j = p * 2 + tt;
                    mma16816(oacc[j], pF[kk], vV[tt * 2], vV[tt * 2 + 1]);
                }
            }
        }
        cs = (cs + 1 == 3) ? 0 : cs + 1;
    }

    #pragma unroll
    for (int hf = 0; hf < 2; ++hf) {
        float il = 1.0f / lrow[hf];
        int row = qbase + wm + (lane >> 2) + hf * 8;
        #pragma unroll
        for (int j = 0; j < 8; ++j) {
            int col = hcol + j * 8 + (lane & 3) * 2;
            float v0 = oacc[j][2*hf]   * il;
            float v1 = oacc[j][2*hf+1] * il;
            *reinterpret_cast<uint32_t*>(&Ohi[(size_t)row * DMODEL + col]) = pack_hf2(v0, v1);
        }
    }
}

// ---------------- launch ----------------------------------------------------
extern "C" void kernel_launch(void* const* d_in, const int* in_sizes, int n_in,
                              void* d_out, int out_size)
{
    (void)in_sizes; (void)n_in; (void)out_size;
    const float* x    = (const float*)d_in[0];
    const float* wq   = (const float*)d_in[1];
    const float* bq   = (const float*)d_in[2];
    const float* wk   = (const float*)d_in[3];
    const float* bk   = (const float*)d_in[4];
    const float* wv   = (const float*)d_in[5];
    const float* bv   = (const float*)d_in[6];
    const float* wo   = (const float*)d_in[7];
    const float* bo   = (const float*)d_in[8];
    const float* ln1g = (const float*)d_in[9];
    const float* ln1b = (const float*)d_in[10];
    const float* w1   = (const float*)d_in[11];
    const float* b1   = (const float*)d_in[12];
    const float* w2   = (const float*)d_in[13];
    const float* b2   = (const float*)d_in[14];
    const float* ln2g = (const float*)d_in[15];
    const float* ln2b = (const float*)d_in[16];
    float* out = (float*)d_out;

    float *xn, *r1, *y, *bqkv;
    cudaGetSymbolAddress((void**)&xn, g_xn);
    cudaGetSymbolAddress((void**)&r1, g_r1);
    cudaGetSymbolAddress((void**)&y,  g_y);
    cudaGetSymbolAddress((void**)&bqkv, g_bqkv);

    __half *xnh,*yh,*qh,*kh,*vh,*ath,*hh;
    __half *wqkvh,*woh,*w1h,*w2h;
    cudaGetSymbolAddress((void**)&xnh, g_xnh);
    cudaGetSymbolAddress((void**)&yh,  g_yh);
    cudaGetSymbolAddress((void**)&qh,  g_qh);
    cudaGetSymbolAddress((void**)&kh,  g_kh);
    cudaGetSymbolAddress((void**)&vh,  g_vh);
    cudaGetSymbolAddress((void**)&ath, g_ath);
    cudaGetSymbolAddress((void**)&hh,  g_hh);
    cudaGetSymbolAddress((void**)&wqkvh, g_wqkvh);
    cudaGetSymbolAddress((void**)&woh, g_woh);
    cudaGetSymbolAddress((void**)&w1h, g_w1h);
    cudaGetSymbolAddress((void**)&w2h, g_w2h);

    cudaFuncSetAttribute(attn_mma, cudaFuncAttributeMaxDynamicSharedMemorySize, ATTN_SMEM);
    cudaFuncSetAttribute(gemm_mma<EPI_QKV3>,  cudaFuncAttributeMaxDynamicSharedMemorySize, GEMM_SMEM);
    cudaFuncSetAttribute(gemm_mma<EPI_RES>,   cudaFuncAttributeMaxDynamicSharedMemorySize, GEMM_SMEM);
    cudaFuncSetAttribute(gemm_mma<EPI_GELUS>, cudaFuncAttributeMaxDynamicSharedMemorySize, GEMM_SMEM);

    conv_qkv_kernel<<<(3*DD4 + 255)/256, 256>>>(wq, wk, wv, bq, bk, bv, wqkvh, bqkv);
    conv_rest_kernel<<<(DD4 + 2*FD4 + 255)/256, 256>>>(wo, w1, w2, woh, w1h, w2h);

    dim3 gQKV(3*DMODEL/128, MROWS/128);   // 24 x 32
    dim3 gD(DMODEL/128, MROWS/128);       // 8 x 32
    dim3 gF(FFDIM/128,  MROWS/128);       // 32 x 32

    ln_conv_kernel<<<MROWS, 256>>>(x, ln1g, ln1b, xn, xnh);
    gemm_mma<EPI_QKV3><<<gQKV, 256, GEMM_SMEM>>>(xnh, wqkvh, bqkv, nullptr, nullptr, qh, kh, vh, MROWS, 3*DMODEL, DMODEL);
    attn_mma<<<dim3(SEQ/128, BATCH*NHEAD), 256, ATTN_SMEM>>>(qh, kh, vh, ath);
    gemm_mma<EPI_RES><<<gD, 256, GEMM_SMEM>>>(ath, woh, bo, xn, r1, nullptr, nullptr, nullptr, MROWS, DMODEL, DMODEL);
    ln_conv_kernel<<<MROWS, 256>>>(r1, ln2g, ln2b, y, yh);
    gemm_mma<EPI_GELUS><<<gF, 256, GEMM_SMEM>>>(yh, w1h, b1, nullptr, nullptr, hh, nullptr, nullptr, MROWS, FFDIM, DMODEL);
    gemm_mma<EPI_RES><<<gD, 256, GEMM_SMEM>>>(hh, w2h, b2, y, out, nullptr, nullptr, nullptr, MROWS, DMODEL, FFDIM);
}

// round 15
// speedup vs baseline: 1.1390x; 1.1390x over previous
#include <cuda_runtime.h>
#include <cuda_fp16.h>
#include <math.h>
#include <stdint.h>

// Problem constants
#define BATCH 2
#define SEQ   2048
#define DMODEL 1024
#define NHEAD 16
#define HDIM  64
#define FFDIM 4096
#define MROWS (BATCH*SEQ)   // 4096
#define LN_EPS 1e-5f

// ---------------- scratch buffers ------------------------------------------
__device__ float g_xn [MROWS*DMODEL];
__device__ float g_r1 [MROWS*DMODEL];
__device__ float g_y  [MROWS*DMODEL];

__device__ __half g_xnh[MROWS*DMODEL];
__device__ __half g_yh [MROWS*DMODEL];
__device__ __half g_qh [MROWS*DMODEL];
__device__ __half g_kh [MROWS*DMODEL];
__device__ __half g_vh [MROWS*DMODEL];
__device__ __half g_ath[MROWS*DMODEL];
__device__ __half g_hh [MROWS*FFDIM];

__device__ __half g_wqkvh[3*DMODEL*DMODEL];   // concat q,k,v weights
__device__ float  g_bqkv [3*DMODEL];          // concat q,k,v biases
__device__ __half g_woh[DMODEL*DMODEL];
__device__ __half g_w1h[FFDIM*DMODEL];
__device__ __half g_w2h[DMODEL*FFDIM];

// ---------------- helpers ---------------------------------------------------
__device__ __forceinline__ uint32_t smem_to_u32(const void* p) {
    uint32_t a;
    asm("{ .reg .u64 t; cvta.to.shared.u64 t, %1; cvt.u32.u64 %0, t; }"
        : "=r"(a) : "l"(p));
    return a;
}
__device__ __forceinline__ void cp16(uint32_t d, const void* s) {
    asm volatile("cp.async.cg.shared.global [%0], [%1], 16;" :: "r"(d), "l"(s) : "memory");
}
#define CP_COMMIT() asm volatile("cp.async.commit_group;" ::: "memory")
#define CP_WAIT1()  asm volatile("cp.async.wait_group 1;" ::: "memory")

__device__ __forceinline__ void ldsm4(uint32_t* r, uint32_t addr) {
    asm volatile("ldmatrix.sync.aligned.m8n8.x4.shared.b16 {%0,%1,%2,%3}, [%4];"
        : "=r"(r[0]), "=r"(r[1]), "=r"(r[2]), "=r"(r[3]) : "r"(addr));
}
__device__ __forceinline__ void ldsm4t(uint32_t* r, uint32_t addr) {
    asm volatile("ldmatrix.sync.aligned.m8n8.x4.trans.shared.b16 {%0,%1,%2,%3}, [%4];"
        : "=r"(r[0]), "=r"(r[1]), "=r"(r[2]), "=r"(r[3]) : "r"(addr));
}
__device__ __forceinline__ void mma16816(float* c, const uint32_t* a,
                                         uint32_t b0, uint32_t b1) {
    asm volatile("mma.sync.aligned.m16n8k16.row.col.f32.f16.f16.f32 "
        "{%0,%1,%2,%3}, {%4,%5,%6,%7}, {%8,%9}, {%0,%1,%2,%3};"
        : "+f"(c[0]), "+f"(c[1]), "+f"(c[2]), "+f"(c[3])
        : "r"(a[0]), "r"(a[1]), "r"(a[2]), "r"(a[3]), "r"(b0), "r"(b1));
}

__device__ __forceinline__ uint32_t pack_hf2(float a, float b) {
    __half2 t;
    t.x = __float2half_rn(a);
    t.y = __float2half_rn(b);
    uint32_t u;
    *reinterpret_cast<__half2*>(&u) = t;
    return u;
}
__device__ __forceinline__ float gelu_exact(float v) {
    return 0.5f * v * (1.0f + erff(v * 0.70710678118654752440f));
}

// ---------------- fused weight converts --------------------------------------
#define DD4 (DMODEL*DMODEL/4)
__global__ __launch_bounds__(256)
void conv_qkv_kernel(const float* __restrict__ wq, const float* __restrict__ wk,
                     const float* __restrict__ wv, const float* __restrict__ bq,
                     const float* __restrict__ bk, const float* __restrict__ bv,
                     __half* __restrict__ dst, float* __restrict__ bdst)
{
    int i = blockIdx.x * blockDim.x + threadIdx.x;
    if (i < 3 * DMODEL / 4) {
        int seg = i / (DMODEL/4), li = i % (DMODEL/4);
        const float* src = (seg == 0) ? bq : (seg == 1) ? bk : bv;
        reinterpret_cast<float4*>(bdst)[i] = reinterpret_cast<const float4*>(src)[li];
    }
    if (i >= 3 * DD4) return;
    int seg = i / DD4, li = i % DD4;
    const float* src = (seg == 0) ? wq : (seg == 1) ? wk : wv;
    float4 v = reinterpret_cast<const float4*>(src)[li];
    uint2 hu;
    hu.x = pack_hf2(v.x, v.y);
    hu.y = pack_hf2(v.z, v.w);
    reinterpret_cast<uint2*>(dst)[i] = hu;
}

#define FD4 (FFDIM*DMODEL/4)
__global__ __launch_bounds__(256)
void conv_rest_kernel(const float* __restrict__ wo, const float* __restrict__ w1,
                      const float* __restrict__ w2, __half* __restrict__ oh,
                      __half* __restrict__ h1, __half* __restrict__ h2)
{
    int i = blockIdx.x * blockDim.x + threadIdx.x;
    if (i >= DD4 + 2 * FD4) return;
    const float* src; __half* dst; int li;
    if (i < DD4)            { src = wo; dst = oh; li = i; }
    else if (i < DD4 + FD4) { src = w1; dst = h1; li = i - DD4; }
    else                    { src = w2; dst = h2; li = i - DD4 - FD4; }
    float4 v = reinterpret_cast<const float4*>(src)[li];
    uint2 hu;
    hu.x = pack_hf2(v.x, v.y);
    hu.y = pack_hf2(v.z, v.w);
    reinterpret_cast<uint2*>(dst)[li] = hu;
}

// ---------------- LayerNorm + fp16 out ---------------------------------------
__global__ __launch_bounds__(256)
void ln_conv_kernel(const float* __restrict__ x, const float* __restrict__ g,
                    const float* __restrict__ b, float* __restrict__ y,
                    __half* __restrict__ yh)
{
    int row = blockIdx.x;
    int tid = threadIdx.x;
    const float4* xr = reinterpret_cast<const float4*>(x + (size_t)row * DMODEL);
    float4 v = xr[tid];

    float s = v.x + v.y + v.z + v.w;
    float q = v.x*v.x + v.y*v.y + v.z*v.z + v.w*v.w;
    #pragma unroll
    for (int o = 16; o > 0; o >>= 1) {
        s += __shfl_down_sync(0xffffffffu, s, o);
        q += __shfl_down_sync(0xffffffffu, q, o);
    }
    __shared__ float ss[8], sq[8];
    int wid = tid >> 5, lane = tid & 31;
    if (lane == 0) { ss[wid] = s; sq[wid] = q; }
    __syncthreads();
    float tot = 0.f, totq = 0.f;
    #pragma unroll
    for (int i = 0; i < 8; ++i) { tot += ss[i]; totq += sq[i]; }

    float mu  = tot * (1.0f / DMODEL);
    float var = totq * (1.0f / DMODEL) - mu * mu;
    float rs  = rsqrtf(var + LN_EPS);

    float4 gg = reinterpret_cast<const float4*>(g)[tid];
    float4 bb = reinterpret_cast<const float4*>(b)[tid];
    float4 o;
    o.x = (v.x - mu) * rs * gg.x + bb.x;
    o.y = (v.y - mu) * rs * gg.y + bb.y;
    o.z = (v.z - mu) * rs * gg.z + bb.z;
    o.w = (v.w - mu) * rs * gg.w + bb.w;
    reinterpret_cast<float4*>(y + (size_t)row * DMODEL)[tid] = o;

    uint2 hu;
    hu.x = pack_hf2(o.x, o.y);
    hu.y = pack_hf2(o.z, o.w);
    reinterpret_cast<uint2*>(yh + (size_t)row * DMODEL)[tid] = hu;
}

// ---------------- warp-MMA GEMM (3-stage pipeline, KC=32) --------------------
#define EPI_RES    1
#define EPI_GELUS  2
#define EPI_QKV3   5

#define GROWB  80
#define MATB   (128 * GROWB)
#define OFF_A  0
#define OFF_W  MATB
#define STAGEB (2*MATB)        // 20480
#define GEMM_SMEM (3*STAGEB)   // 61440 -> 2 CTAs = 122880

template<int EPI>
__global__ __launch_bounds__(256, 2)
void gemm_mma(const __half* __restrict__ A, const __half* __restrict__ W,
              const float* __restrict__ bias, const float* __restrict__ res,
              float* __restrict__ Cf, __half* __restrict__ Chi,
              __half* __restrict__ C2, __half* __restrict__ C3,
              int M, int N, int K)
{
    extern __shared__ char smc[];
    uint32_t sb = smem_to_u32(smc);
    int tid  = threadIdx.x;
    int lane = tid & 31;
    int warp = tid >> 5;
    int n0 = blockIdx.x * 128;
    int m0 = blockIdx.y * 128;
    int wm = (warp >> 2) * 64;
    int wn = (warp & 3) * 32;

    int r  = tid >> 1;
    int hf = tid & 1;
    const __half* gA = A + (size_t)(m0 + r) * K + hf * 16;
    const __half* gW = W + (size_t)(n0 + r) * K + hf * 16;
    uint32_t sdst = sb + r * GROWB + hf * 32;

    float acc[4][4][4];
    #pragma unroll
    for (int mi = 0; mi < 4; ++mi)
        #pragma unroll
        for (int nj = 0; nj < 4; ++nj)
            #pragma unroll
            for (int e = 0; e < 4; ++e) acc[mi][nj][e] = 0.f;

    uint32_t lmo = (uint32_t)((lane & 15) * GROWB + (lane >> 4) * 16);
    int nch = K / 32;

    // prologue: stages 0 and 1, each its own group
    {
        cp16(sdst + OFF_A, gA);  cp16(sdst + OFF_A + 16, gA + 8);
        cp16(sdst + OFF_W, gW);  cp16(sdst + OFF_W + 16, gW + 8);
        CP_COMMIT();
        uint32_t d2 = sdst + STAGEB;
        cp16(d2 + OFF_A, gA + 32);  cp16(d2 + OFF_A + 16, gA + 40);
        cp16(d2 + OFF_W, gW + 32);  cp16(d2 + OFF_W + 16, gW + 40);
        CP_COMMIT();
    }

    int cs = 0;
    for (int c = 0; c < nch; ++c) {
        CP_WAIT1();            // stage c landed (per-thread)
        __syncthreads();       // visible to all; all warps done with stage c-1

        if (c + 2 < nch) {
            int ps = cs + 2; if (ps >= 3) ps -= 3;
            size_t ko = (size_t)(c + 2) * 32;
            uint32_t d2 = sdst + ps * STAGEB;
            cp16(d2 + OFF_A, gA + ko);  cp16(d2 + OFF_A + 16, gA + ko + 8);
            cp16(d2 + OFF_W, gW + ko);  cp16(d2 + OFF_W + 16, gW + ko + 8);
        }
        CP_COMMIT();

        uint32_t stgb = sb + cs * STAGEB;
        #pragma unroll
        for (int ks = 0; ks < 2; ++ks) {
            uint32_t kb = ks * 32;
            uint32_t aF[4][4], bW[2][4];
            #pragma unroll
            for (int mi = 0; mi < 4; ++mi) {
                uint32_t ra = (wm + mi * 16) * GROWB + lmo + kb;
                ldsm4(aF[mi], stgb + OFF_A + ra);
            }
            #pragma unroll
            for (int p = 0; p < 2; ++p) {
                uint32_t rb = (wn + p * 16) * GROWB + lmo + kb;
                ldsm4(bW[p], stgb + OFF_W + rb);
            }
            #pragma unroll
            for (int mi = 0; mi < 4; ++mi) {
                #pragma unroll
                for (int nj = 0; nj < 4; ++nj) {
                    uint32_t b0 = bW[nj >> 1][nj & 1];
                    uint32_t b1 = bW[nj >> 1][(nj & 1) + 2];
                    mma16816(acc[mi][nj], aF[mi], b0, b1);
                }
            }
        }
        cs = (cs + 1 == 3) ? 0 : cs + 1;
    }

    int gid  = lane >> 2;
    int tid4 = lane & 3;
    float b2v[4][2];
    #pragma unroll
    for (int nj = 0; nj < 4; ++nj) {
        int col = n0 + wn + nj * 8 + tid4 * 2;
        b2v[nj][0] = bias[col];
        b2v[nj][1] = bias[col + 1];
    }
    __half* qdst = Chi;
    if (EPI == EPI_QKV3) {
        qdst = (n0 < DMODEL) ? Chi : ((n0 < 2*DMODEL) ? C2 : C3);
    }
    #pragma unroll
    for (int mi = 0; mi < 4; ++mi) {
        #pragma unroll
        for (int half = 0; half < 2; ++half) {
            int row = m0 + wm + mi * 16 + gid + half * 8;
            #pragma unroll
            for (int nj = 0; nj < 4; ++nj) {
                int col = n0 + wn + nj * 8 + tid4 * 2;
                float v0 = acc[mi][nj][half * 2 + 0] + b2v[nj][0];
                float v1 = acc[mi][nj][half * 2 + 1] + b2v[nj][1];
                if (EPI == EPI_RES) {
                    float2 rv = *reinterpret_cast<const float2*>(&res[(size_t)row * N + col]);
                    v0 += rv.x; v1 += rv.y;
                    float2 o; o.x = v0; o.y = v1;
                    *reinterpret_cast<float2*>(&Cf[(size_t)row * N + col]) = o;
                } else if (EPI == EPI_QKV3) {
                    int lcol = col & (DMODEL - 1);
                    *reinterpret_cast<uint32_t*>(&qdst[(size_t)row * DMODEL + lcol]) = pack_hf2(v0, v1);
                } else {
                    if (EPI == EPI_GELUS) { v0 = gelu_exact(v0); v1 = gelu_exact(v1); }
                    *reinterpret_cast<uint32_t*>(&Chi[(size_t)row * N + col]) = pack_hf2(v0, v1);
                }
            }
        }
    }
}

// ---------------- MMA flash attention (3-stage KV pipeline) ------------------
#define QST 72                         // smem row stride in fp16 elems (144B)
#define AQ  0
#define AKV0 (128*QST)                 // stage base
#define KVSTG (2*64*QST)               // elems per stage (K, V)
#define AOF_K 0
#define AOF_V (64*QST)
#define ATTN_SMEM ((128*QST + 3*KVSTG) * 2)   // 73728 bytes

__global__ __launch_bounds__(256, 2)
void attn_mma(const __half* __restrict__ Qh, const __half* __restrict__ Kh,
              const __half* __restrict__ Vh, __half* __restrict__ Ohi)
{
    extern __shared__ __half sma[];
    uint32_t sb = smem_to_u32(sma);

    int tid  = threadIdx.x;
    int lane = tid & 31;
    int warp = tid >> 5;
    int bh = blockIdx.y;
    int b = bh >> 4, h = bh & 15;
    int qbase  = b * SEQ + blockIdx.x * 128;
    int kvbase = b * SEQ;
    int hcol   = h * HDIM;
    int wm = warp * 16;

    int krr = tid >> 2;
    int kc4 = (tid & 3) * 16;
    uint32_t kdst = sb + (krr * QST + kc4) * 2;
    size_t kgo = (size_t)hcol + kc4;

    {
        int rr = tid >> 1, cc2 = (tid & 1) * 4;
        const __half* gq = Qh + (size_t)(qbase + rr) * DMODEL + hcol + cc2 * 8;
        uint32_t dq = sb + (rr * QST + cc2 * 8) * 2;
        #pragma unroll
        for (int c = 0; c < 4; ++c)
            cp16(dq + AQ * 2 + c * 16, gq + c * 8);

        size_t grow = (size_t)(kvbase + krr) * DMODEL + kgo;
        uint32_t st = kdst + AKV0 * 2;
        cp16(st + AOF_K*2, Kh + grow);  cp16(st + AOF_K*2 + 16, Kh + grow + 8);
        cp16(st + AOF_V*2, Vh + grow);  cp16(st + AOF_V*2 + 16, Vh + grow + 8);
        CP_COMMIT();

        grow = (size_t)(kvbase + 64 + krr) * DMODEL + kgo;
        st = kdst + (AKV0 + KVSTG) * 2;
        cp16(st + AOF_K*2, Kh + grow);  cp16(st + AOF_K*2 + 16, Kh + grow + 8);
        cp16(st + AOF_V*2, Vh + grow);  cp16(st + AOF_V*2 + 16, Vh + grow + 8);
        CP_COMMIT();
    }

    float oacc[8][4];
    #pragma unroll
    for (int j = 0; j < 8; ++j)
        #pragma unroll
        for (int e = 0; e < 4; ++e) oacc[j][e] = 0.f;
    float mrow[2] = {-1e30f, -1e30f};
    float lrow[2] = {0.f, 0.f};

    uint32_t lmo = (uint32_t)((lane & 15) * QST * 2 + (lane >> 4) * 16);
    const float scale = 0.125f;

    const int NT = SEQ / 64;
    int cs = 0;
    for (int t = 0; t < NT; ++t) {
        CP_WAIT1();
        __syncthreads();

        if (t + 2 < NT) {
            int ps = cs + 2; if (ps >= 3) ps -= 3;
            size_t grow = (size_t)(kvbase + (t + 2) * 64 + krr) * DMODEL + kgo;
            uint32_t st = kdst + (AKV0 + ps * KVSTG) * 2;
            cp16(st + AOF_K*2, Kh + grow);  cp16(st + AOF_K*2 + 16, Kh + grow + 8);
            cp16(st + AOF_V*2, Vh + grow);  cp16(st + AOF_V*2 + 16, Vh + grow + 8);
        }
        CP_COMMIT();

        uint32_t kvb = sb + (AKV0 + cs * KVSTG) * 2;

        float sacc[8][4];
        #pragma unroll
        for (int j = 0; j < 8; ++j)
            #pragma unroll
            for (int e = 0; e < 4; ++e) sacc[j][e] = 0.f;

        #pragma unroll
        for (int kk = 0; kk < 4; ++kk) {
            uint32_t aQ[4], bK[4];
            uint32_t qa = sb + wm * QST * 2 + lmo + kk * 32;
            ldsm4(aQ, qa + AQ * 2);
            #pragma unroll
            for (int p = 0; p < 4; ++p) {
                uint32_t ka = kvb + p * 16 * QST * 2 + lmo + kk * 32;
                ldsm4(bK, ka + AOF_K * 2);
                #pragma unroll
                for (int tt = 0; tt < 2; ++tt) {
                    int j = p * 2 + tt;
                    mma16816(sacc[j], aQ, bK[tt], bK[tt + 2]);
                }
            }
        }

        float alpha[2];
        #pragma unroll
        for (int hf = 0; hf < 2; ++hf) {
            float mv = mrow[hf];
            #pragma unroll
            for (int j = 0; j < 8; ++j) {
                sacc[j][2*hf]   *= scale;
                sacc[j][2*hf+1] *= scale;
                mv = fmaxf(mv, fmaxf(sacc[j][2*hf], sacc[j][2*hf+1]));
            }
            mv = fmaxf(mv, __shfl_xor_sync(0xffffffffu, mv, 1));
            mv = fmaxf(mv, __shfl_xor_sync(0xffffffffu, mv, 2));
            alpha[hf] = __expf(mrow[hf] - mv);
            float ls = 0.f;
            #pragma unroll
            for (int j = 0; j < 8; ++j) {
                sacc[j][2*hf]   = __expf(sacc[j][2*hf]   - mv);
                sacc[j][2*hf+1] = __expf(sacc[j][2*hf+1] - mv);
                ls += sacc[j][2*hf] + sacc[j][2*hf+1];
            }
            ls += __shfl_xor_sync(0xffffffffu, ls, 1);
            ls += __shfl_xor_sync(0xffffffffu, ls, 2);
            lrow[hf] = lrow[hf] * alpha[hf] + ls;
            mrow[hf] = mv;
            #pragma unroll
            for (int j = 0; j < 8; ++j) {
                oacc[j][2*hf]   *= alpha[hf];
                oacc[j][2*hf+1] *= alpha[hf];
            }
        }

        uint32_t pF[4][4];
        #pragma unroll
        for (int kk = 0; kk < 4; ++kk) {
            int j0 = 2 * kk, j1 = 2 * kk + 1;
            pF[kk][0] = pack_hf2(sacc[j0][0], sacc[j0][1]);
            pF[kk][1] = pack_hf2(sacc[j0][2], sacc[j0][3]);
            pF[kk][2] = pack_hf2(sacc[j1][0], sacc[j1][1]);
            pF[kk][3] = pack_hf2(sacc[j1][2], sacc[j1][3]);
        }

        #pragma unroll
        for (int kk = 0; kk < 4; ++kk) {
            #pragma unroll
            for (int p = 0; p < 4; ++p) {
                uint32_t va = kvb + kk * 16 * QST * 2 + lmo + p * 32;
                uint32_t vV[4];
                ldsm4t(vV, va + AOF_V * 2);
                #pragma unroll
                for (int tt = 0; tt < 2; ++tt) {
                    int j = p * 2 + tt;
                    mma16816(oacc[j], pF[kk], vV[tt * 2], vV[tt * 2 + 1]);
                }
            }
        }
        cs = (cs + 1 == 3) ? 0 : cs + 1;
    }

    #pragma unroll
    for (int hf = 0; hf < 2; ++hf) {
        float il = 1.0f / lrow[hf];
        int row = qbase + wm + (lane >> 2) + hf * 8;
        #pragma unroll
        for (int j = 0; j < 8; ++j) {
            int col = hcol + j * 8 + (lane & 3) * 2;
            float v0 = oacc[j][2*hf]   * il;
            float v1 = oacc[j][2*hf+1] * il;
            *reinterpret_cast<uint32_t*>(&Ohi[(size_t)row * DMODEL + col]) = pack_hf2(v0, v1);
        }
    }
}

// ---------------- launch ----------------------------------------------------
extern "C" void kernel_launch(void* const* d_in, const int* in_sizes, int n_in,
                              void* d_out, int out_size)
{
    (void)in_sizes; (void)n_in; (void)out_size;
    const float* x    = (const float*)d_in[0];
    const float* wq   = (const float*)d_in[1];
    const float* bq   = (const float*)d_in[2];
    const float* wk   = (const float*)d_in[3];
    const float* bk   = (const float*)d_in[4];
    const float* wv   = (const float*)d_in[5];
    const float* bv   = (const float*)d_in[6];
    const float* wo   = (const float*)d_in[7];
    const float* bo   = (const float*)d_in[8];
    const float* ln1g = (const float*)d_in[9];
    const float* ln1b = (const float*)d_in[10];
    const float* w1   = (const float*)d_in[11];
    const float* b1   = (const float*)d_in[12];
    const float* w2   = (const float*)d_in[13];
    const float* b2   = (const float*)d_in[14];
    const float* ln2g = (const float*)d_in[15];
    const float* ln2b = (const float*)d_in[16];
    float* out = (float*)d_out;

    float *xn, *r1, *y, *bqkv;
    cudaGetSymbolAddress((void**)&xn, g_xn);
    cudaGetSymbolAddress((void**)&r1, g_r1);
    cudaGetSymbolAddress((void**)&y,  g_y);
    cudaGetSymbolAddress((void**)&bqkv, g_bqkv);

    __half *xnh,*yh,*qh,*kh,*vh,*ath,*hh;
    __half *wqkvh,*woh,*w1h,*w2h;
    cudaGetSymbolAddress((void**)&xnh, g_xnh);
    cudaGetSymbolAddress((void**)&yh,  g_yh);
    cudaGetSymbolAddress((void**)&qh,  g_qh);
    cudaGetSymbolAddress((void**)&kh,  g_kh);
    cudaGetSymbolAddress((void**)&vh,  g_vh);
    cudaGetSymbolAddress((void**)&ath, g_ath);
    cudaGetSymbolAddress((void**)&hh,  g_hh);
    cudaGetSymbolAddress((void**)&wqkvh, g_wqkvh);
    cudaGetSymbolAddress((void**)&woh, g_woh);
    cudaGetSymbolAddress((void**)&w1h, g_w1h);
    cudaGetSymbolAddress((void**)&w2h, g_w2h);

    cudaFuncSetAttribute(attn_mma, cudaFuncAttributeMaxDynamicSharedMemorySize, ATTN_SMEM);
    cudaFuncSetAttribute(gemm_mma<EPI_QKV3>,  cudaFuncAttributeMaxDynamicSharedMemorySize, GEMM_SMEM);
    cudaFuncSetAttribute(gemm_mma<EPI_RES>,   cudaFuncAttributeMaxDynamicSharedMemorySize, GEMM_SMEM);
    cudaFuncSetAttribute(gemm_mma<EPI_GELUS>, cudaFuncAttributeMaxDynamicSharedMemorySize, GEMM_SMEM);

    // Side stream for conv_rest (only needed before the wo-projection GEMM).
    static cudaStream_t s2 = nullptr;
    static cudaEvent_t evF = nullptr, evJ = nullptr;
    if (s2 == nullptr) {
        cudaStreamCreateWithFlags(&s2, cudaStreamNonBlocking);
        cudaEventCreateWithFlags(&evF, cudaEventDisableTiming);
        cudaEventCreateWithFlags(&evJ, cudaEventDisableTiming);
    }

    dim3 gQKV(3*DMODEL/128, MROWS/128);   // 24 x 32
    dim3 gD(DMODEL/128, MROWS/128);       // 8 x 32
    dim3 gF(FFDIM/128,  MROWS/128);       // 32 x 32

    // fork: conv_rest on s2, overlapping LN1 + QKV + attention
    cudaEventRecord(evF, 0);
    cudaStreamWaitEvent(s2, evF, 0);
    conv_rest_kernel<<<(DD4 + 2*FD4 + 255)/256, 256, 0, s2>>>(wo, w1, w2, woh, w1h, w2h);
    cudaEventRecord(evJ, s2);

    conv_qkv_kernel<<<(3*DD4 + 255)/256, 256>>>(wq, wk, wv, bq, bk, bv, wqkvh, bqkv);
    ln_conv_kernel<<<MROWS, 256>>>(x, ln1g, ln1b, xn, xnh);
    gemm_mma<EPI_QKV3><<<gQKV, 256, GEMM_SMEM>>>(xnh, wqkvh, bqkv, nullptr, nullptr, qh, kh, vh, MROWS, 3*DMODEL, DMODEL);
    attn_mma<<<dim3(SEQ/128, BATCH*NHEAD), 256, ATTN_SMEM>>>(qh, kh, vh, ath);

    // join before the first consumer of woh/w1h/w2h
    cudaStreamWaitEvent(0, evJ, 0);
    gemm_mma<EPI_RES><<<gD, 256, GEMM_SMEM>>>(ath, woh, bo, xn, r1, nullptr, nullptr, nullptr, MROWS, DMODEL, DMODEL);
    ln_conv_kernel<<<MROWS, 256>>>(r1, ln2g, ln2b, y, yh);
    gemm_mma<EPI_GELUS><<<gF, 256, GEMM_SMEM>>>(yh, w1h, b1, nullptr, nullptr, hh, nullptr, nullptr, MROWS, FFDIM, DMODEL);
    gemm_mma<EPI_RES><<<gD, 256, GEMM_SMEM>>>(hh, w2h, b2, y, out, nullptr, nullptr, nullptr, MROWS, DMODEL, FFDIM);
}

// round 16
// speedup vs baseline: 1.2183x; 1.0696x over previous
#include <cuda_runtime.h>
#include <cuda_fp16.h>
#include <math.h>
#include <stdint.h>

// Problem constants
#define BATCH 2
#define SEQ   2048
#define DMODEL 1024
#define NHEAD 16
#define HDIM  64
#define FFDIM 4096
#define MROWS (BATCH*SEQ)   // 4096
#define HROWS (MROWS/2)     // 2048 rows per batch
#define LN_EPS 1e-5f

// ---------------- scratch buffers ------------------------------------------
__device__ float g_xn [MROWS*DMODEL];
__device__ float g_r1 [MROWS*DMODEL];
__device__ float g_y  [MROWS*DMODEL];

__device__ __half g_xnh[MROWS*DMODEL];
__device__ __half g_yh [MROWS*DMODEL];
__device__ __half g_qh [MROWS*DMODEL];
__device__ __half g_kh [MROWS*DMODEL];
__device__ __half g_vh [MROWS*DMODEL];
__device__ __half g_ath[MROWS*DMODEL];
__device__ __half g_hh [MROWS*FFDIM];

__device__ __half g_wqkvh[3*DMODEL*DMODEL];   // concat q,k,v weights
__device__ float  g_bqkv [3*DMODEL];          // concat q,k,v biases
__device__ __half g_woh[DMODEL*DMODEL];
__device__ __half g_w1h[FFDIM*DMODEL];
__device__ __half g_w2h[DMODEL*FFDIM];

// ---------------- helpers ---------------------------------------------------
__device__ __forceinline__ uint32_t smem_to_u32(const void* p) {
    uint32_t a;
    asm("{ .reg .u64 t; cvta.to.shared.u64 t, %1; cvt.u32.u64 %0, t; }"
        : "=r"(a) : "l"(p));
    return a;
}
__device__ __forceinline__ void cp16(uint32_t d, const void* s) {
    asm volatile("cp.async.cg.shared.global [%0], [%1], 16;" :: "r"(d), "l"(s) : "memory");
}
#define CP_COMMIT() asm volatile("cp.async.commit_group;" ::: "memory")
#define CP_WAIT1()  asm volatile("cp.async.wait_group 1;" ::: "memory")

__device__ __forceinline__ void ldsm4(uint32_t* r, uint32_t addr) {
    asm volatile("ldmatrix.sync.aligned.m8n8.x4.shared.b16 {%0,%1,%2,%3}, [%4];"
        : "=r"(r[0]), "=r"(r[1]), "=r"(r[2]), "=r"(r[3]) : "r"(addr));
}
__device__ __forceinline__ void ldsm4t(uint32_t* r, uint32_t addr) {
    asm volatile("ldmatrix.sync.aligned.m8n8.x4.trans.shared.b16 {%0,%1,%2,%3}, [%4];"
        : "=r"(r[0]), "=r"(r[1]), "=r"(r[2]), "=r"(r[3]) : "r"(addr));
}
__device__ __forceinline__ void mma16816(float* c, const uint32_t* a,
                                         uint32_t b0, uint32_t b1) {
    asm volatile("mma.sync.aligned.m16n8k16.row.col.f32.f16.f16.f32 "
        "{%0,%1,%2,%3}, {%4,%5,%6,%7}, {%8,%9}, {%0,%1,%2,%3};"
        : "+f"(c[0]), "+f"(c[1]), "+f"(c[2]), "+f"(c[3])
        : "r"(a[0]), "r"(a[1]), "r"(a[2]), "r"(a[3]), "r"(b0), "r"(b1));
}

__device__ __forceinline__ uint32_t pack_hf2(float a, float b) {
    __half2 t;
    t.x = __float2half_rn(a);
    t.y = __float2half_rn(b);
    uint32_t u;
    *reinterpret_cast<__half2*>(&u) = t;
    return u;
}
__device__ __forceinline__ float gelu_exact(float v) {
    return 0.5f * v * (1.0f + erff(v * 0.70710678118654752440f));
}

// ---------------- fused weight converts --------------------------------------
#define DD4 (DMODEL*DMODEL/4)
__global__ __launch_bounds__(256)
void conv_qkv_kernel(const float* __restrict__ wq, const float* __restrict__ wk,
                     const float* __restrict__ wv, const float* __restrict__ bq,
                     const float* __restrict__ bk, const float* __restrict__ bv,
                     __half* __restrict__ dst, float* __restrict__ bdst)
{
    int i = blockIdx.x * blockDim.x + threadIdx.x;
    if (i < 3 * DMODEL / 4) {
        int seg = i / (DMODEL/4), li = i % (DMODEL/4);
        const float* src = (seg == 0) ? bq : (seg == 1) ? bk : bv;
        reinterpret_cast<float4*>(bdst)[i] = reinterpret_cast<const float4*>(src)[li];
    }
    if (i >= 3 * DD4) return;
    int seg = i / DD4, li = i % DD4;
    const float* src = (seg == 0) ? wq : (seg == 1) ? wk : wv;
    float4 v = reinterpret_cast<const float4*>(src)[li];
    uint2 hu;
    hu.x = pack_hf2(v.x, v.y);
    hu.y = pack_hf2(v.z, v.w);
    reinterpret_cast<uint2*>(dst)[i] = hu;
}

#define FD4 (FFDIM*DMODEL/4)
__global__ __launch_bounds__(256)
void conv_rest_kernel(const float* __restrict__ wo, const float* __restrict__ w1,
                      const float* __restrict__ w2, __half* __restrict__ oh,
                      __half* __restrict__ h1, __half* __restrict__ h2)
{
    int i = blockIdx.x * blockDim.x + threadIdx.x;
    if (i >= DD4 + 2 * FD4) return;
    const float* src; __half* dst; int li;
    if (i < DD4)            { src = wo; dst = oh; li = i; }
    else if (i < DD4 + FD4) { src = w1; dst = h1; li = i - DD4; }
    else                    { src = w2; dst = h2; li = i - DD4 - FD4; }
    float4 v = reinterpret_cast<const float4*>(src)[li];
    uint2 hu;
    hu.x = pack_hf2(v.x, v.y);
    hu.y = pack_hf2(v.z, v.w);
    reinterpret_cast<uint2*>(dst)[li] = hu;
}

// ---------------- LayerNorm + fp16 out (row offset) --------------------------
__global__ __launch_bounds__(256)
void ln_conv_kernel(const float* __restrict__ x, const float* __restrict__ g,
                    const float* __restrict__ b, float* __restrict__ y,
                    __half* __restrict__ yh, int row0)
{
    int row = row0 + blockIdx.x;
    int tid = threadIdx.x;
    const float4* xr = reinterpret_cast<const float4*>(x + (size_t)row * DMODEL);
    float4 v = xr[tid];

    float s = v.x + v.y + v.z + v.w;
    float q = v.x*v.x + v.y*v.y + v.z*v.z + v.w*v.w;
    #pragma unroll
    for (int o = 16; o > 0; o >>= 1) {
        s += __shfl_down_sync(0xffffffffu, s, o);
        q += __shfl_down_sync(0xffffffffu, q, o);
    }
    __shared__ float ss[8], sq[8];
    int wid = tid >> 5, lane = tid & 31;
    if (lane == 0) { ss[wid] = s; sq[wid] = q; }
    __syncthreads();
    float tot = 0.f, totq = 0.f;
    #pragma unroll
    for (int i = 0; i < 8; ++i) { tot += ss[i]; totq += sq[i]; }

    float mu  = tot * (1.0f / DMODEL);
    float var = totq * (1.0f / DMODEL) - mu * mu;
    float rs  = rsqrtf(var + LN_EPS);

    float4 gg = reinterpret_cast<const float4*>(g)[tid];
    float4 bb = reinterpret_cast<const float4*>(b)[tid];
    float4 o;
    o.x = (v.x - mu) * rs * gg.x + bb.x;
    o.y = (v.y - mu) * rs * gg.y + bb.y;
    o.z = (v.z - mu) * rs * gg.z + bb.z;
    o.w = (v.w - mu) * rs * gg.w + bb.w;
    reinterpret_cast<float4*>(y + (size_t)row * DMODEL)[tid] = o;

    uint2 hu;
    hu.x = pack_hf2(o.x, o.y);
    hu.y = pack_hf2(o.z, o.w);
    reinterpret_cast<uint2*>(yh + (size_t)row * DMODEL)[tid] = hu;
}

// ---------------- warp-MMA GEMM (3-stage pipeline, KC=32, m offset) ----------
#define EPI_RES    1
#define EPI_GELUS  2
#define EPI_QKV3   5

#define GROWB  80
#define MATB   (128 * GROWB)
#define OFF_A  0
#define OFF_W  MATB
#define STAGEB (2*MATB)        // 20480
#define GEMM_SMEM (3*STAGEB)   // 61440 -> 2 CTAs = 122880

template<int EPI>
__global__ __launch_bounds__(256, 2)
void gemm_mma(const __half* __restrict__ A, const __half* __restrict__ W,
              const float* __restrict__ bias, const float* __restrict__ res,
              float* __restrict__ Cf, __half* __restrict__ Chi,
              __half* __restrict__ C2, __half* __restrict__ C3,
              int mbase, int M, int N, int K)
{
    extern __shared__ char smc[];
    uint32_t sb = smem_to_u32(smc);
    int tid  = threadIdx.x;
    int lane = tid & 31;
    int warp = tid >> 5;
    int n0 = blockIdx.x * 128;
    int m0 = mbase + blockIdx.y * 128;
    int wm = (warp >> 2) * 64;
    int wn = (warp & 3) * 32;

    int r  = tid >> 1;
    int hf = tid & 1;
    const __half* gA = A + (size_t)(m0 + r) * K + hf * 16;
    const __half* gW = W + (size_t)(n0 + r) * K + hf * 16;
    uint32_t sdst = sb + r * GROWB + hf * 32;

    float acc[4][4][4];
    #pragma unroll
    for (int mi = 0; mi < 4; ++mi)
        #pragma unroll
        for (int nj = 0; nj < 4; ++nj)
            #pragma unroll
            for (int e = 0; e < 4; ++e) acc[mi][nj][e] = 0.f;

    uint32_t lmo = (uint32_t)((lane & 15) * GROWB + (lane >> 4) * 16);
    int nch = K / 32;

    {
        cp16(sdst + OFF_A, gA);  cp16(sdst + OFF_A + 16, gA + 8);
        cp16(sdst + OFF_W, gW);  cp16(sdst + OFF_W + 16, gW + 8);
        CP_COMMIT();
        uint32_t d2 = sdst + STAGEB;
        cp16(d2 + OFF_A, gA + 32);  cp16(d2 + OFF_A + 16, gA + 40);
        cp16(d2 + OFF_W, gW + 32);  cp16(d2 + OFF_W + 16, gW + 40);
        CP_COMMIT();
    }

    int cs = 0;
    for (int c = 0; c < nch; ++c) {
        CP_WAIT1();
        __syncthreads();

        if (c + 2 < nch) {
            int ps = cs + 2; if (ps >= 3) ps -= 3;
            size_t ko = (size_t)(c + 2) * 32;
            uint32_t d2 = sdst + ps * STAGEB;
            cp16(d2 + OFF_A, gA + ko);  cp16(d2 + OFF_A + 16, gA + ko + 8);
            cp16(d2 + OFF_W, gW + ko);  cp16(d2 + OFF_W + 16, gW + ko + 8);
        }
        CP_COMMIT();

        uint32_t stgb = sb + cs * STAGEB;
        #pragma unroll
        for (int ks = 0; ks < 2; ++ks) {
            uint32_t kb = ks * 32;
            uint32_t aF[4][4], bW[2][4];
            #pragma unroll
            for (int mi = 0; mi < 4; ++mi) {
                uint32_t ra = (wm + mi * 16) * GROWB + lmo + kb;
                ldsm4(aF[mi], stgb + OFF_A + ra);
            }
            #pragma unroll
            for (int p = 0; p < 2; ++p) {
                uint32_t rb = (wn + p * 16) * GROWB + lmo + kb;
                ldsm4(bW[p], stgb + OFF_W + rb);
            }
            #pragma unroll
            for (int mi = 0; mi < 4; ++mi) {
                #pragma unroll
                for (int nj = 0; nj < 4; ++nj) {
                    uint32_t b0 = bW[nj >> 1][nj & 1];
                    uint32_t b1 = bW[nj >> 1][(nj & 1) + 2];
                    mma16816(acc[mi][nj], aF[mi], b0, b1);
                }
            }
        }
        cs = (cs + 1 == 3) ? 0 : cs + 1;
    }

    int gid  = lane >> 2;
    int tid4 = lane & 3;
    float b2v[4][2];
    #pragma unroll
    for (int nj = 0; nj < 4; ++nj) {
        int col = n0 + wn + nj * 8 + tid4 * 2;
        b2v[nj][0] = bias[col];
        b2v[nj][1] = bias[col + 1];
    }
    __half* qdst = Chi;
    if (EPI == EPI_QKV3) {
        qdst = (n0 < DMODEL) ? Chi : ((n0 < 2*DMODEL) ? C2 : C3);
    }
    #pragma unroll
    for (int mi = 0; mi < 4; ++mi) {
        #pragma unroll
        for (int half = 0; half < 2; ++half) {
            int row = m0 + wm + mi * 16 + gid + half * 8;
            #pragma unroll
            for (int nj = 0; nj < 4; ++nj) {
                int col = n0 + wn + nj * 8 + tid4 * 2;
                float v0 = acc[mi][nj][half * 2 + 0] + b2v[nj][0];
                float v1 = acc[mi][nj][half * 2 + 1] + b2v[nj][1];
                if (EPI == EPI_RES) {
                    float2 rv = *reinterpret_cast<const float2*>(&res[(size_t)row * N + col]);
                    v0 += rv.x; v1 += rv.y;
                    float2 o; o.x = v0; o.y = v1;
                    *reinterpret_cast<float2*>(&Cf[(size_t)row * N + col]) = o;
                } else if (EPI == EPI_QKV3) {
                    int lcol = col & (DMODEL - 1);
                    *reinterpret_cast<uint32_t*>(&qdst[(size_t)row * DMODEL + lcol]) = pack_hf2(v0, v1);
                } else {
                    if (EPI == EPI_GELUS) { v0 = gelu_exact(v0); v1 = gelu_exact(v1); }
                    *reinterpret_cast<uint32_t*>(&Chi[(size_t)row * N + col]) = pack_hf2(v0, v1);
                }
            }
        }
    }
}

// ---------------- MMA flash attention (3-stage KV pipeline, batch select) ----
#define QST 72                         // smem row stride in fp16 elems (144B)
#define AQ  0
#define AKV0 (128*QST)                 // stage base
#define KVSTG (2*64*QST)               // elems per stage (K, V)
#define AOF_K 0
#define AOF_V (64*QST)
#define ATTN_SMEM ((128*QST + 3*KVSTG) * 2)   // 73728 bytes

__global__ __launch_bounds__(256, 2)
void attn_mma(const __half* __restrict__ Qh, const __half* __restrict__ Kh,
              const __half* __restrict__ Vh, __half* __restrict__ Ohi, int bsel)
{
    extern __shared__ __half sma[];
    uint32_t sb = smem_to_u32(sma);

    int tid  = threadIdx.x;
    int lane = tid & 31;
    int warp = tid >> 5;
    int b = bsel, h = blockIdx.y;
    int qbase  = b * SEQ + blockIdx.x * 128;
    int kvbase = b * SEQ;
    int hcol   = h * HDIM;
    int wm = warp * 16;

    int krr = tid >> 2;
    int kc4 = (tid & 3) * 16;
    uint32_t kdst = sb + (krr * QST + kc4) * 2;
    size_t kgo = (size_t)hcol + kc4;

    {
        int rr = tid >> 1, cc2 = (tid & 1) * 4;
        const __half* gq = Qh + (size_t)(qbase + rr) * DMODEL + hcol + cc2 * 8;
        uint32_t dq = sb + (rr * QST + cc2 * 8) * 2;
        #pragma unroll
        for (int c = 0; c < 4; ++c)
            cp16(dq + AQ * 2 + c * 16, gq + c * 8);

        size_t grow = (size_t)(kvbase + krr) * DMODEL + kgo;
        uint32_t st = kdst + AKV0 * 2;
        cp16(st + AOF_K*2, Kh + grow);  cp16(st + AOF_K*2 + 16, Kh + grow + 8);
        cp16(st + AOF_V*2, Vh + grow);  cp16(st + AOF_V*2 + 16, Vh + grow + 8);
        CP_COMMIT();

        grow = (size_t)(kvbase + 64 + krr) * DMODEL + kgo;
        st = kdst + (AKV0 + KVSTG) * 2;
        cp16(st + AOF_K*2, Kh + grow);  cp16(st + AOF_K*2 + 16, Kh + grow + 8);
        cp16(st + AOF_V*2, Vh + grow);  cp16(st + AOF_V*2 + 16, Vh + grow + 8);
        CP_COMMIT();
    }

    float oacc[8][4];
    #pragma unroll
    for (int j = 0; j < 8; ++j)
        #pragma unroll
        for (int e = 0; e < 4; ++e) oacc[j][e] = 0.f;
    float mrow[2] = {-1e30f, -1e30f};
    float lrow[2] = {0.f, 0.f};

    uint32_t lmo = (uint32_t)((lane & 15) * QST * 2 + (lane >> 4) * 16);
    const float scale = 0.125f;

    const int NT = SEQ / 64;
    int cs = 0;
    for (int t = 0; t < NT; ++t) {
        CP_WAIT1();
        __syncthreads();

        if (t + 2 < NT) {
            int ps = cs + 2; if (ps >= 3) ps -= 3;
            size_t grow = (size_t)(kvbase + (t + 2) * 64 + krr) * DMODEL + kgo;
            uint32_t st = kdst + (AKV0 + ps * KVSTG) * 2;
            cp16(st + AOF_K*2, Kh + grow);  cp16(st + AOF_K*2 + 16, Kh + grow + 8);
            cp16(st + AOF_V*2, Vh + grow);  cp16(st + AOF_V*2 + 16, Vh + grow + 8);
        }
        CP_COMMIT();

        uint32_t kvb = sb + (AKV0 + cs * KVSTG) * 2;

        float sacc[8][4];
        #pragma unroll
        for (int j = 0; j < 8; ++j)
            #pragma unroll
            for (int e = 0; e < 4; ++e) sacc[j][e] = 0.f;

        #pragma unroll
        for (int kk = 0; kk < 4; ++kk) {
            uint32_t aQ[4], bK[4];
            uint32_t qa = sb + wm * QST * 2 + lmo + kk * 32;
            ldsm4(aQ, qa + AQ * 2);
            #pragma unroll
            for (int p = 0; p < 4; ++p) {
                uint32_t ka = kvb + p * 16 * QST * 2 + lmo + kk * 32;
                ldsm4(bK, ka + AOF_K * 2);
                #pragma unroll
                for (int tt = 0; tt < 2; ++tt) {
                    int j = p * 2 + tt;
                    mma16816(sacc[j], aQ, bK[tt], bK[tt + 2]);
                }
            }
        }

        float alpha[2];
        #pragma unroll
        for (int hf = 0; hf < 2; ++hf) {
            float mv = mrow[hf];
            #pragma unroll
            for (int j = 0; j < 8; ++j) {
                sacc[j][2*hf]   *= scale;
                sacc[j][2*hf+1] *= scale;
                mv = fmaxf(mv, fmaxf(sacc[j][2*hf], sacc[j][2*hf+1]));
            }
            mv = fmaxf(mv, __shfl_xor_sync(0xffffffffu, mv, 1));
            mv = fmaxf(mv, __shfl_xor_sync(0xffffffffu, mv, 2));
            alpha[hf] = __expf(mrow[hf] - mv);
            float ls = 0.f;
            #pragma unroll
            for (int j = 0; j < 8; ++j) {
                sacc[j][2*hf]   = __expf(sacc[j][2*hf]   - mv);
                sacc[j][2*hf+1] = __expf(sacc[j][2*hf+1] - mv);
                ls += sacc[j][2*hf] + sacc[j][2*hf+1];
            }
            ls += __shfl_xor_sync(0xffffffffu, ls, 1);
            ls += __shfl_xor_sync(0xffffffffu, ls, 2);
            lrow[hf] = lrow[hf] * alpha[hf] + ls;
            mrow[hf] = mv;
            #pragma unroll
            for (int j = 0; j < 8; ++j) {
                oacc[j][2*hf]   *= alpha[hf];
                oacc[j][2*hf+1] *= alpha[hf];
            }
        }

        uint32_t pF[4][4];
        #pragma unroll
        for (int kk = 0; kk < 4; ++kk) {
            int j0 = 2 * kk, j1 = 2 * kk + 1;
            pF[kk][0] = pack_hf2(sacc[j0][0], sacc[j0][1]);
            pF[kk][1] = pack_hf2(sacc[j0][2], sacc[j0][3]);
            pF[kk][2] = pack_hf2(sacc[j1][0], sacc[j1][1]);
            pF[kk][3] = pack_hf2(sacc[j1][2], sacc[j1][3]);
        }

        #pragma unroll
        for (int kk = 0; kk < 4; ++kk) {
            #pragma unroll
            for (int p = 0; p < 4; ++p) {
                uint32_t va = kvb + kk * 16 * QST * 2 + lmo + p * 32;
                uint32_t vV[4];
                ldsm4t(vV, va + AOF_V * 2);
                #pragma unroll
                for (int tt = 0; tt < 2; ++tt) {
                    int j = p * 2 + tt;
                    mma16816(oacc[j], pF[kk], vV[tt * 2], vV[tt * 2 + 1]);
                }
            }
        }
        cs = (cs + 1 == 3) ? 0 : cs + 1;
    }

    #pragma unroll
    for (int hf = 0; hf < 2; ++hf) {
        float il = 1.0f / lrow[hf];
        int row = qbase + wm + (lane >> 2) + hf * 8;
        #pragma unroll
        for (int j = 0; j < 8; ++j) {
            int col = hcol + j * 8 + (lane & 3) * 2;
            float v0 = oacc[j][2*hf]   * il;
            float v1 = oacc[j][2*hf+1] * il;
            *reinterpret_cast<uint32_t*>(&Ohi[(size_t)row * DMODEL + col]) = pack_hf2(v0, v1);
        }
    }
}

// ---------------- launch ----------------------------------------------------
extern "C" void kernel_launch(void* const* d_in, const int* in_sizes, int n_in,
                              void* d_out, int out_size)
{
    (void)in_sizes; (void)n_in; (void)out_size;
    const float* x    = (const float*)d_in[0];
    const float* wq   = (const float*)d_in[1];
    const float* bq   = (const float*)d_in[2];
    const float* wk   = (const float*)d_in[3];
    const float* bk   = (const float*)d_in[4];
    const float* wv   = (const float*)d_in[5];
    const float* bv   = (const float*)d_in[6];
    const float* wo   = (const float*)d_in[7];
    const float* bo   = (const float*)d_in[8];
    const float* ln1g = (const float*)d_in[9];
    const float* ln1b = (const float*)d_in[10];
    const float* w1   = (const float*)d_in[11];
    const float* b1   = (const float*)d_in[12];
    const float* w2   = (const float*)d_in[13];
    const float* b2   = (const float*)d_in[14];
    const float* ln2g = (const float*)d_in[15];
    const float* ln2b = (const float*)d_in[16];
    float* out = (float*)d_out;

    float *xn, *r1, *y, *bqkv;
    cudaGetSymbolAddress((void**)&xn, g_xn);
    cudaGetSymbolAddress((void**)&r1, g_r1);
    cudaGetSymbolAddress((void**)&y,  g_y);
    cudaGetSymbolAddress((void**)&bqkv, g_bqkv);

    __half *xnh,*yh,*qh,*kh,*vh,*ath,*hh;
    __half *wqkvh,*woh,*w1h,*w2h;
    cudaGetSymbolAddress((void**)&xnh, g_xnh);
    cudaGetSymbolAddress((void**)&yh,  g_yh);
    cudaGetSymbolAddress((void**)&qh,  g_qh);
    cudaGetSymbolAddress((void**)&kh,  g_kh);
    cudaGetSymbolAddress((void**)&vh,  g_vh);
    cudaGetSymbolAddress((void**)&ath, g_ath);
    cudaGetSymbolAddress((void**)&hh,  g_hh);
    cudaGetSymbolAddress((void**)&wqkvh, g_wqkvh);
    cudaGetSymbolAddress((void**)&woh, g_woh);
    cudaGetSymbolAddress((void**)&w1h, g_w1h);
    cudaGetSymbolAddress((void**)&w2h, g_w2h);

    cudaFuncSetAttribute(attn_mma, cudaFuncAttributeMaxDynamicSharedMemorySize, ATTN_SMEM);
    cudaFuncSetAttribute(gemm_mma<EPI_QKV3>,  cudaFuncAttributeMaxDynamicSharedMemorySize, GEMM_SMEM);
    cudaFuncSetAttribute(gemm_mma<EPI_RES>,   cudaFuncAttributeMaxDynamicSharedMemorySize, GEMM_SMEM);
    cudaFuncSetAttribute(gemm_mma<EPI_GELUS>, cudaFuncAttributeMaxDynamicSharedMemorySize, GEMM_SMEM);

    static cudaStream_t sA = nullptr, sB = nullptr;
    static cudaEvent_t evW = nullptr, evR = nullptr, evA = nullptr, evB = nullptr, evF = nullptr;
    if (sA == nullptr) {
        cudaStreamCreateWithFlags(&sA, cudaStreamNonBlocking);
        cudaStreamCreateWithFlags(&sB, cudaStreamNonBlocking);
        cudaEventCreateWithFlags(&evW, cudaEventDisableTiming);
        cudaEventCreateWithFlags(&evR, cudaEventDisableTiming);
        cudaEventCreateWithFlags(&evA, cudaEventDisableTiming);
        cudaEventCreateWithFlags(&evB, cudaEventDisableTiming);
        cudaEventCreateWithFlags(&evF, cudaEventDisableTiming);
    }

    dim3 gQKVh(3*DMODEL/128, HROWS/128);   // 24 x 16 per batch
    dim3 gDh(DMODEL/128, HROWS/128);       // 8 x 16
    dim3 gFh(FFDIM/128,  HROWS/128);       // 32 x 16
    dim3 gAttn(SEQ/128, NHEAD);            // 16 x 16 per batch

    // weight converts on default stream; fork point
    cudaEventRecord(evF, 0);
    cudaStreamWaitEvent(sA, evF, 0);
    cudaStreamWaitEvent(sB, evF, 0);
    conv_qkv_kernel<<<(3*DD4 + 255)/256, 256>>>(wq, wk, wv, bq, bk, bv, wqkvh, bqkv);
    cudaEventRecord(evW, 0);
    conv_rest_kernel<<<(DD4 + 2*FD4 + 255)/256, 256>>>(wo, w1, w2, woh, w1h, w2h);
    cudaEventRecord(evR, 0);

    // ---- per-batch pipelines ----
    cudaStream_t strm[2] = {sA, sB};
    for (int b = 0; b < 2; ++b) {
        cudaStream_t s = strm[b];
        int r0 = b * HROWS;
        ln_conv_kernel<<<HROWS, 256, 0, s>>>(x, ln1g, ln1b, xn, xnh, r0);
        cudaStreamWaitEvent(s, evW, 0);
        gemm_mma<EPI_QKV3><<<gQKVh, 256, GEMM_SMEM, s>>>(xnh, wqkvh, bqkv, nullptr, nullptr, qh, kh, vh, r0, MROWS, 3*DMODEL, DMODEL);
        attn_mma<<<gAttn, 256, ATTN_SMEM, s>>>(qh, kh, vh, ath, b);
        cudaStreamWaitEvent(s, evR, 0);
        gemm_mma<EPI_RES><<<gDh, 256, GEMM_SMEM, s>>>(ath, woh, bo, xn, r1, nullptr, nullptr, nullptr, r0, MROWS, DMODEL, DMODEL);
        ln_conv_kernel<<<HROWS, 256, 0, s>>>(r1, ln2g, ln2b, y, yh, r0);
        gemm_mma<EPI_GELUS><<<gFh, 256, GEMM_SMEM, s>>>(yh, w1h, b1, nullptr, nullptr, hh, nullptr, nullptr, r0, MROWS, FFDIM, DMODEL);
        gemm_mma<EPI_RES><<<gDh, 256, GEMM_SMEM, s>>>(hh, w2h, b2, y, out, nullptr, nullptr, nullptr, r0, MROWS, DMODEL, FFDIM);
    }

    // join
    cudaEventRecord(evA, sA);
    cudaEventRecord(evB, sB);
    cudaStreamWaitEvent(0, evA, 0);
    cudaStreamWaitEvent(0, evB, 0);
}